// round 6
// baseline (speedup 1.0000x reference)
#include <cuda_runtime.h>
#include <cuda_bf16.h>
#include <cstdint>

// Problem dims (fixed)
#define Bk 64
#define Sk 2048
#define Ik 64
#define Hk 128

typedef unsigned long long ull;

// ---------- scratch (no allocations allowed) ----------
__device__ float g_wx[Bk * Sk * Hk];    // 64 MB: input projection for current layer
__device__ float g_out0[Bk * Sk * Hk];  // 64 MB: layer-0 outputs

// ---------- packed f32x2 helpers ----------
static __device__ __forceinline__ ull pack2(float x, float y) {
    ull r; asm("mov.b64 %0, {%1, %2};" : "=l"(r) : "f"(x), "f"(y)); return r;
}
static __device__ __forceinline__ ull fma2(ull a, ull b, ull c) {
    ull d; asm("fma.rn.f32x2 %0, %1, %2, %3;" : "=l"(d) : "l"(a), "l"(b), "l"(c)); return d;
}
static __device__ __forceinline__ ull add2(ull a, ull b) {
    ull d; asm("add.rn.f32x2 %0, %1, %2;" : "=l"(d) : "l"(a), "l"(b)); return d;
}
static __device__ __forceinline__ float red2(ull a) {
    float x, y; asm("mov.b64 {%0, %1}, %2;" : "=f"(x), "=f"(y) : "l"(a)); return x + y;
}

// fast sigmoid / tanh (ex2.approx-based, ~1e-7 rel err)
static __device__ __forceinline__ float fsigm(float x) {
    float e = __expf(-x);
    return __fdividef(1.0f, 1.0f + e);
}
static __device__ __forceinline__ float ftanh(float x) {
    float e = __expf(2.0f * x);                 // inf-safe: 2/inf -> 0 -> tanh=1
    return 1.0f - __fdividef(2.0f, e + 1.0f);
}

// ============================================================
// GEMM: Y[M,128] = X[M,KIN] @ W[KIN,128], f32, packed f32x2
// block tile: 16 rows x 128 cols, 256 threads (8 rows/thread)
// W staged through smem in 32-kp stages (32 KB) -> static smem
// stays under 48 KB, no cudaFuncSetAttribute needed.
// ============================================================
template <int KIN>
__global__ __launch_bounds__(256) void gemm_kernel(
    const float* __restrict__ X, const float* __restrict__ W,
    float* __restrict__ Y)
{
    constexpr int KP = KIN / 2;          // packed-k length (32 or 64)
    constexpr int SK = 32;               // kp per W stage
    constexpr int NST = KP / SK;         // 1 (KIN=64) or 2 (KIN=128)

    __shared__ ull ws2[SK * 128];        // 32 KB: W stage, pair-packed along k
    __shared__ ull xs2[16 * KP];         // <=8 KB: X tile, pair-packed along k

    const int tid = threadIdx.x;
    const int j = tid & 127;
    const int rh = tid >> 7;             // 0 or 1
    const int row0 = blockIdx.x * 16;
    const int rb = rh * 8;

    // stage X tile once (rows contiguous in k -> float2 loads already paired)
    const float2* X2 = (const float2*)X;
    for (int idx = tid; idx < 16 * KP; idx += 256) {
        int r = idx / KP, kp = idx - r * KP;
        float2 v = X2[(size_t)(row0 + r) * KP + kp];
        xs2[idx] = pack2(v.x, v.y);
    }

    ull acc[8];
#pragma unroll
    for (int r = 0; r < 8; r++) acc[r] = 0ull;

#pragma unroll
    for (int s = 0; s < NST; s++) {
        __syncthreads();   // protects xs2 staging (s=0) / prior ws2 reads (s>0)
        for (int idx = tid; idx < SK * 128; idx += 256) {
            int kpl = idx >> 7, jj = idx & 127;
            int kp = s * SK + kpl;
            ws2[idx] = pack2(W[(2 * kp) * 128 + jj], W[(2 * kp + 1) * 128 + jj]);
        }
        __syncthreads();

#pragma unroll 4
        for (int kpl = 0; kpl < SK; kpl++) {
            ull wv = ws2[kpl * 128 + j];               // conflict-free
            const int kp = s * SK + kpl;
#pragma unroll
            for (int r = 0; r < 8; r++)                // broadcast reads
                acc[r] = fma2(xs2[(rb + r) * KP + kp], wv, acc[r]);
        }
    }

#pragma unroll
    for (int r = 0; r < 8; r++)
        Y[(size_t)(row0 + rb + r) * 128 + j] = red2(acc[r]);
}

// ============================================================
// Recurrent scan: TWO batch elements per CTA (256 threads).
// sub = tid>>7 selects the batch element; j = tid&127 the unit.
// u column held in registers (64 packed f32x2), h double-buffered
// in smem per sub-batch, wx streamed with 8-step register buffer.
// The two recurrences run in lockstep via the shared barrier; one
// recurrence's FMA stream fills the other's MUFU/reduction tail.
// ============================================================
__global__ __launch_bounds__(256) void scan_kernel(
    const float* __restrict__ wx,     // [B,S,H]
    const float* __restrict__ u,      // [H,H] row-major
    const float* __restrict__ bg, const float* __restrict__ bu,
    const float* __restrict__ zeta, const float* __restrict__ nu,
    const float* __restrict__ lambd, const float* __restrict__ gamma,
    float* __restrict__ out,          // [B,S,H]
    float* __restrict__ hT)           // [B,H]
{
    const int sub = threadIdx.x >> 7;            // 0 or 1
    const int j = threadIdx.x & 127;
    const int b = blockIdx.x * 2 + sub;

    __shared__ __align__(16) float hs[2][2][Hk]; // [buf][sub][H]

    // u column j -> registers, packed in k-pairs (same for both subs)
    ull up[Hk / 2];
#pragma unroll
    for (int i = 0; i < Hk / 2; i++)
        up[i] = pack2(u[(2 * i) * Hk + j], u[(2 * i + 1) * Hk + j]);

    const float bgj = bg[j];
    const float buj = bu[j];
    const float sz = fsigm(zeta[0]);
    const float sn = fsigm(nu[0]);
    const float gc = fminf(fmaxf(gamma[0], 0.0f), 1.0f);
    const float c0 = (1.0f - gc) * lambd[0];

    const float* wrow = wx + (size_t)b * Sk * Hk + j;
    float* orow = out + (size_t)b * Sk * Hk + j;

    float hold = 0.0f;
    hs[0][sub][j] = 0.0f;

    float wc[8], wn[8];
#pragma unroll
    for (int d = 0; d < 8; d++) wc[d] = __ldcs(&wrow[d * Hk]);

    __syncthreads();

    int p = 0;
    for (int tc = 0; tc < Sk; tc += 8) {
        // prefetch next chunk of wx (register double buffer; MLP=8)
        const int tn = (tc + 8 < Sk) ? (tc + 8) : tc;
#pragma unroll
        for (int d = 0; d < 8; d++) wn[d] = __ldcs(&wrow[(tn + d) * Hk]);

#pragma unroll
        for (int d = 0; d < 8; d++) {
            const ulonglong2* hq = (const ulonglong2*)hs[p][sub];
            ull a0 = 0ull, a1 = 0ull, a2 = 0ull, a3 = 0ull;
#pragma unroll
            for (int i = 0; i < 32; i += 2) {
                ulonglong2 h0 = hq[i];      // broadcast LDS.128
                ulonglong2 h1 = hq[i + 1];
                a0 = fma2(h0.x, up[2 * i + 0], a0);
                a1 = fma2(h0.y, up[2 * i + 1], a1);
                a2 = fma2(h1.x, up[2 * i + 2], a2);
                a3 = fma2(h1.y, up[2 * i + 3], a3);
            }
            a0 = add2(a0, a2);
            a1 = add2(a1, a3);
            const float acc = red2(add2(a0, a1));

            const float pre = wc[d] + acc;
            const float z = fsigm(pre + bgj);
            const float hh = ftanh(pre + buj);
            const float hnew = z * hold + (sz * (1.0f - z) + sn) * hh;
            const float hc = fmaf(gc, hnew, c0);

            hold = hc;
            hs[p ^ 1][sub][j] = hc;       // STS first: gates next step via barrier
            orow[(tc + d) * Hk] = hc;     // STG after: fire-and-forget
            __syncthreads();
            p ^= 1;
        }
#pragma unroll
        for (int d = 0; d < 8; d++) wc[d] = wn[d];
    }

    hT[b * Hk + j] = hold;
}

// ============================================================
// launch
// ============================================================
extern "C" void kernel_launch(void* const* d_in, const int* in_sizes, int n_in,
                              void* d_out, int out_size)
{
    const float* x      = (const float*)d_in[0];
    const float* w0     = (const float*)d_in[1];
    const float* u0     = (const float*)d_in[2];
    const float* bg0    = (const float*)d_in[3];
    const float* bu0    = (const float*)d_in[4];
    const float* zeta0  = (const float*)d_in[5];
    const float* nu0    = (const float*)d_in[6];
    const float* lambd0 = (const float*)d_in[7];
    const float* gamma0 = (const float*)d_in[8];
    const float* w1     = (const float*)d_in[9];
    const float* u1     = (const float*)d_in[10];
    const float* bg1    = (const float*)d_in[11];
    const float* bu1    = (const float*)d_in[12];
    const float* zeta1  = (const float*)d_in[13];
    const float* nu1    = (const float*)d_in[14];
    const float* lambd1 = (const float*)d_in[15];
    const float* gamma1 = (const float*)d_in[16];

    float* out = (float*)d_out;
    const size_t OFF_HN = (size_t)Bk * Sk * Hk;  // out1 first, then h_n [2,B,H]

    float* wxbuf = nullptr;
    float* out0 = nullptr;
    cudaGetSymbolAddress((void**)&wxbuf, g_wx);
    cudaGetSymbolAddress((void**)&out0, g_out0);

    const int M = Bk * Sk;  // 131072 rows

    // layer 0
    gemm_kernel<Ik><<<M / 16, 256>>>(x, w0, wxbuf);
    scan_kernel<<<Bk / 2, 256>>>(wxbuf, u0, bg0, bu0, zeta0, nu0, lambd0, gamma0,
                                 out0, out + OFF_HN);
    // layer 1
    gemm_kernel<Hk><<<M / 16, 256>>>(out0, w1, wxbuf);
    scan_kernel<<<Bk / 2, 256>>>(wxbuf, u1, bg1, bu1, zeta1, nu1, lambd1, gamma1,
                                 out, out + OFF_HN + Bk * Hk);
}

// round 15
// speedup vs baseline: 1.5423x; 1.5423x over previous
#include <cuda_runtime.h>
#include <cuda_bf16.h>
#include <cstdint>

// Problem dims (fixed)
#define Bk 64
#define Sk 2048
#define Ik 64
#define Hk 128

typedef unsigned long long ull;

// ---------- scratch (no allocations allowed) ----------
__device__ float g_wx[Bk * Sk * Hk];    // 64 MB: input projection for current layer
__device__ float g_out0[Bk * Sk * Hk];  // 64 MB: layer-0 outputs

// ---------- packed f32x2 helpers ----------
static __device__ __forceinline__ ull pack2(float x, float y) {
    ull r; asm("mov.b64 %0, {%1, %2};" : "=l"(r) : "f"(x), "f"(y)); return r;
}
static __device__ __forceinline__ ull fma2(ull a, ull b, ull c) {
    ull d; asm("fma.rn.f32x2 %0, %1, %2, %3;" : "=l"(d) : "l"(a), "l"(b), "l"(c)); return d;
}
static __device__ __forceinline__ ull add2(ull a, ull b) {
    ull d; asm("add.rn.f32x2 %0, %1, %2;" : "=l"(d) : "l"(a), "l"(b)); return d;
}
static __device__ __forceinline__ float red2(ull a) {
    float x, y; asm("mov.b64 {%0, %1}, %2;" : "=f"(x), "=f"(y) : "l"(a)); return x + y;
}

// fast sigmoid / tanh (ex2.approx-based, ~1e-7 rel err)
static __device__ __forceinline__ float fsigm(float x) {
    float e = __expf(-x);
    return __fdividef(1.0f, 1.0f + e);
}
static __device__ __forceinline__ float ftanh(float x) {
    float e = __expf(2.0f * x);                 // inf-safe: 2/inf -> 0 -> tanh=1
    return 1.0f - __fdividef(2.0f, e + 1.0f);
}

// ============================================================
// GEMM: Y[M,128] = X[M,KIN] @ W[KIN,128], f32, packed f32x2
// block tile: 32 rows x 128 cols, 256 threads (16 rows/thread)
// W staged through smem in 32-kp stages (32 KB); xs2 <=16 KB;
// total static smem <=48 KB -> no cudaFuncSetAttribute needed.
// ============================================================
template <int KIN>
__global__ __launch_bounds__(256) void gemm_kernel(
    const float* __restrict__ X, const float* __restrict__ W,
    float* __restrict__ Y)
{
    constexpr int KP = KIN / 2;          // packed-k length (32 or 64)
    constexpr int SK = 32;               // kp per W stage
    constexpr int NST = KP / SK;         // 1 (KIN=64) or 2 (KIN=128)
    constexpr int RT = 32;               // rows per CTA tile

    __shared__ ull ws2[SK * 128];        // 32 KB: W stage, pair-packed along k
    __shared__ ull xs2[RT * KP];         // 8/16 KB: X tile, pair-packed along k

    const int tid = threadIdx.x;
    const int j = tid & 127;
    const int rh = tid >> 7;             // 0 or 1
    const int row0 = blockIdx.x * RT;
    const int rb = rh * 16;

    // stage X tile once (rows contiguous in k -> float2 loads already paired)
    const float2* X2 = (const float2*)X;
    for (int idx = tid; idx < RT * KP; idx += 256) {
        int r = idx / KP, kp = idx - r * KP;
        float2 v = X2[(size_t)(row0 + r) * KP + kp];
        xs2[idx] = pack2(v.x, v.y);
    }

    ull acc[16];
#pragma unroll
    for (int r = 0; r < 16; r++) acc[r] = 0ull;

#pragma unroll
    for (int s = 0; s < NST; s++) {
        __syncthreads();   // protects xs2 staging (s=0) / prior ws2 reads (s>0)
        for (int idx = tid; idx < SK * 128; idx += 256) {
            int kpl = idx >> 7, jj = idx & 127;
            int kp = s * SK + kpl;
            ws2[idx] = pack2(W[(2 * kp) * 128 + jj], W[(2 * kp + 1) * 128 + jj]);
        }
        __syncthreads();

#pragma unroll 2
        for (int kpl = 0; kpl < SK; kpl++) {
            ull wv = ws2[kpl * 128 + j];               // conflict-free
            const int kp = s * SK + kpl;
#pragma unroll
            for (int r = 0; r < 16; r++)               // broadcast reads
                acc[r] = fma2(xs2[(rb + r) * KP + kp], wv, acc[r]);
        }
    }

#pragma unroll
    for (int r = 0; r < 16; r++)
        Y[(size_t)(row0 + rb + r) * 128 + j] = red2(acc[r]);
}

// ============================================================
// Recurrent scan: ONE batch element per CTA (128 threads, 64 CTAs
// -> 64 SMs). Per SMSP per step: 32 LDS.128 + 64 fma2 -- spreading
// over 64 SMs halves both vs the 2-per-CTA lockstep variant.
// u column in registers (64 packed f32x2), h double-buffered in
// smem, wx streamed with 8-step register double buffer.
// ============================================================
__global__ __launch_bounds__(128) void scan_kernel(
    const float* __restrict__ wx,     // [B,S,H]
    const float* __restrict__ u,      // [H,H] row-major
    const float* __restrict__ bg, const float* __restrict__ bu,
    const float* __restrict__ zeta, const float* __restrict__ nu,
    const float* __restrict__ lambd, const float* __restrict__ gamma,
    float* __restrict__ out,          // [B,S,H]
    float* __restrict__ hT)           // [B,H]
{
    const int b = blockIdx.x;
    const int j = threadIdx.x;

    __shared__ __align__(16) float hs[2][Hk];

    // u column j -> registers, packed in k-pairs
    ull up[Hk / 2];
#pragma unroll
    for (int i = 0; i < Hk / 2; i++)
        up[i] = pack2(u[(2 * i) * Hk + j], u[(2 * i + 1) * Hk + j]);

    const float bgj = bg[j];
    const float buj = bu[j];
    const float sz = fsigm(zeta[0]);
    const float sn = fsigm(nu[0]);
    const float gc = fminf(fmaxf(gamma[0], 0.0f), 1.0f);
    const float c0 = (1.0f - gc) * lambd[0];

    const float* wrow = wx + (size_t)b * Sk * Hk + j;
    float* orow = out + (size_t)b * Sk * Hk + j;

    float hold = 0.0f;
    hs[0][j] = 0.0f;

    float wc[8], wn[8];
#pragma unroll
    for (int d = 0; d < 8; d++) wc[d] = __ldcs(&wrow[d * Hk]);

    __syncthreads();

    int p = 0;
    for (int tc = 0; tc < Sk; tc += 8) {
        // prefetch next chunk of wx (register double buffer; MLP=8)
        const int tn = (tc + 8 < Sk) ? (tc + 8) : tc;
#pragma unroll
        for (int d = 0; d < 8; d++) wn[d] = __ldcs(&wrow[(tn + d) * Hk]);

#pragma unroll
        for (int d = 0; d < 8; d++) {
            const ulonglong2* hq = (const ulonglong2*)hs[p];
            ull a0 = 0ull, a1 = 0ull, a2 = 0ull, a3 = 0ull;
#pragma unroll
            for (int i = 0; i < 32; i += 2) {
                ulonglong2 h0 = hq[i];      // broadcast LDS.128
                ulonglong2 h1 = hq[i + 1];
                a0 = fma2(h0.x, up[2 * i + 0], a0);
                a1 = fma2(h0.y, up[2 * i + 1], a1);
                a2 = fma2(h1.x, up[2 * i + 2], a2);
                a3 = fma2(h1.y, up[2 * i + 3], a3);
            }
            a0 = add2(a0, a2);
            a1 = add2(a1, a3);
            const float acc = red2(add2(a0, a1));

            const float pre = wc[d] + acc;
            const float z = fsigm(pre + bgj);
            const float hh = ftanh(pre + buj);
            const float hnew = z * hold + (sz * (1.0f - z) + sn) * hh;
            const float hc = fmaf(gc, hnew, c0);

            hold = hc;
            hs[p ^ 1][j] = hc;            // STS first: gates next step via barrier
            orow[(tc + d) * Hk] = hc;     // STG after: fire-and-forget
            __syncthreads();
            p ^= 1;
        }
#pragma unroll
        for (int d = 0; d < 8; d++) wc[d] = wn[d];
    }

    hT[b * Hk + j] = hold;
}

// ============================================================
// launch
// ============================================================
extern "C" void kernel_launch(void* const* d_in, const int* in_sizes, int n_in,
                              void* d_out, int out_size)
{
    const float* x      = (const float*)d_in[0];
    const float* w0     = (const float*)d_in[1];
    const float* u0     = (const float*)d_in[2];
    const float* bg0    = (const float*)d_in[3];
    const float* bu0    = (const float*)d_in[4];
    const float* zeta0  = (const float*)d_in[5];
    const float* nu0    = (const float*)d_in[6];
    const float* lambd0 = (const float*)d_in[7];
    const float* gamma0 = (const float*)d_in[8];
    const float* w1     = (const float*)d_in[9];
    const float* u1     = (const float*)d_in[10];
    const float* bg1    = (const float*)d_in[11];
    const float* bu1    = (const float*)d_in[12];
    const float* zeta1  = (const float*)d_in[13];
    const float* nu1    = (const float*)d_in[14];
    const float* lambd1 = (const float*)d_in[15];
    const float* gamma1 = (const float*)d_in[16];

    float* out = (float*)d_out;
    const size_t OFF_HN = (size_t)Bk * Sk * Hk;  // out1 first, then h_n [2,B,H]

    float* wxbuf = nullptr;
    float* out0 = nullptr;
    cudaGetSymbolAddress((void**)&wxbuf, g_wx);
    cudaGetSymbolAddress((void**)&out0, g_out0);

    const int M = Bk * Sk;  // 131072 rows

    // layer 0
    gemm_kernel<Ik><<<M / 32, 256>>>(x, w0, wxbuf);
    scan_kernel<<<Bk, 128>>>(wxbuf, u0, bg0, bu0, zeta0, nu0, lambd0, gamma0,
                             out0, out + OFF_HN);
    // layer 1
    gemm_kernel<Hk><<<M / 32, 256>>>(out0, w1, wxbuf);
    scan_kernel<<<Bk, 128>>>(wxbuf, u1, bg1, bu1, zeta1, nu1, lambd1, gamma1,
                             out, out + OFF_HN + Bk * Hk);
}